// round 14
// baseline (speedup 1.0000x reference)
#include <cuda_runtime.h>
#include <math.h>

#define N_MAX 100000
typedef unsigned long long ull;
typedef unsigned int u32;

// ---- scratch ----
__device__ __align__(16) float g_A[N_MAX * 32];
__device__ __align__(16) float g_B[N_MAX * 32];
__device__ __align__(16) float g_sumenc[N_MAX * 4];
__device__ __align__(16) float g_cnt[N_MAX];
__device__ __align__(16) float g_sumout[N_MAX * 4];
__device__ __align__(16) float g_stats[8];

// ---- helpers ----
__device__ __forceinline__ void red4(float* p, float a, float b, float c, float d) {
    asm volatile("red.global.add.v4.f32 [%0], {%1,%2,%3,%4};"
                 :: "l"(p), "f"(a), "f"(b), "f"(c), "f"(d) : "memory");
}
__device__ __forceinline__ void redf(float* p, float v) {
    asm volatile("red.global.add.f32 [%0], %1;" :: "l"(p), "f"(v) : "memory");
}
__device__ __forceinline__ u32 bfpack(float y, float x) {
    u32 r; asm("cvt.rn.bf16x2.f32 %0, %1, %2;" : "=r"(r) : "f"(y), "f"(x)); return r;
}
__device__ __forceinline__ void bsplit(float x, float y, u32& h, u32& l) {
    h = bfpack(y, x);
    float xr = x - __uint_as_float(h << 16);
    float yr = y - __uint_as_float(h & 0xFFFF0000u);
    l = bfpack(yr, xr);
}
__device__ __forceinline__ void mma16(float* d, const u32* a, u32 b0, u32 b1) {
    asm volatile("mma.sync.aligned.m16n8k16.row.col.f32.bf16.bf16.f32 "
                 "{%0,%1,%2,%3},{%4,%5,%6,%7},{%8,%9},{%0,%1,%2,%3};"
                 : "+f"(d[0]), "+f"(d[1]), "+f"(d[2]), "+f"(d[3])
                 : "r"(a[0]), "r"(a[1]), "r"(a[2]), "r"(a[3]), "r"(b0), "r"(b1));
}
__device__ __forceinline__ void lds128(unsigned addr, u32& a, u32& b, u32& c, u32& d) {
    asm volatile("ld.shared.v4.u32 {%0,%1,%2,%3}, [%4];"
                 : "=r"(a), "=r"(b), "=r"(c), "=r"(d) : "r"(addr));
}
__device__ __forceinline__ void ldmx4(u32* r, unsigned addr) {
    asm volatile("ldmatrix.sync.aligned.m8n8.x4.shared.b16 {%0,%1,%2,%3}, [%4];"
                 : "=r"(r[0]), "=r"(r[1]), "=r"(r[2]), "=r"(r[3]) : "r"(addr));
}

// ---- K0: zero stats only ----
__global__ void k_zero_s() {
    if (threadIdx.x < 8) g_stats[threadIdx.x] = 0.f;
}

// ---- K1: batchnorm statistics ----
__global__ void k_stats(const float4* __restrict__ x, int n) {
    float sx = 0, sy = 0, sz = 0, sw = 0, qx = 0, qy = 0, qz = 0, qw = 0;
    for (int i = blockIdx.x * blockDim.x + threadIdx.x; i < n; i += gridDim.x * blockDim.x) {
        float4 v = x[i];
        sx += v.x; sy += v.y; sz += v.z; sw += v.w;
        qx += v.x * v.x; qy += v.y * v.y; qz += v.z * v.z; qw += v.w * v.w;
    }
    #pragma unroll
    for (int off = 16; off; off >>= 1) {
        sx += __shfl_down_sync(0xffffffffu, sx, off);
        sy += __shfl_down_sync(0xffffffffu, sy, off);
        sz += __shfl_down_sync(0xffffffffu, sz, off);
        sw += __shfl_down_sync(0xffffffffu, sw, off);
        qx += __shfl_down_sync(0xffffffffu, qx, off);
        qy += __shfl_down_sync(0xffffffffu, qy, off);
        qz += __shfl_down_sync(0xffffffffu, qz, off);
        qw += __shfl_down_sync(0xffffffffu, qw, off);
    }
    if ((threadIdx.x & 31) == 0) {
        atomicAdd(&g_stats[0], sx); atomicAdd(&g_stats[1], sy);
        atomicAdd(&g_stats[2], sz); atomicAdd(&g_stats[3], sw);
        atomicAdd(&g_stats[4], qx); atomicAdd(&g_stats[5], qy);
        atomicAdd(&g_stats[6], qz); atomicAdd(&g_stats[7], qw);
    }
}

// ---- K2: BN + encoder layer-1 split (also zeroes sumenc/cnt) ----
__global__ void k_pre(const float4* __restrict__ x,
                      const float* __restrict__ gamma, const float* __restrict__ beta,
                      const float* __restrict__ eW1, const float* __restrict__ eb1,
                      int n, float invN) {
    __shared__ float sWd[128], sWb[128], sb1[32], sScale[4], sShift[4];
    int t = threadIdx.x;
    if (t < 128) {
        int c = t >> 5, o = t & 31;
        float wa = eW1[c * 32 + o], wb = eW1[(4 + c) * 32 + o];
        sWd[t] = wa - wb; sWb[t] = wb;
    }
    if (t < 32) sb1[t] = eb1[t];
    if (t < 4) {
        float m = g_stats[t] * invN;
        float v = g_stats[4 + t] * invN - m * m;
        float s = rsqrtf(v + 1e-5f) * gamma[t];
        sScale[t] = s; sShift[t] = beta[t] - m * s;
    }
    __syncthreads();
    for (int i = blockIdx.x * blockDim.x + t; i < n; i += gridDim.x * blockDim.x) {
        float4 xv = x[i];
        float xn[4];
        xn[0] = xv.x * sScale[0] + sShift[0];
        xn[1] = xv.y * sScale[1] + sShift[1];
        xn[2] = xv.z * sScale[2] + sShift[2];
        xn[3] = xv.w * sScale[3] + sShift[3];
        float a[32], b[32];
        #pragma unroll
        for (int o = 0; o < 32; o++) {
            float av = sb1[o], bv = 0.f;
            #pragma unroll
            for (int c = 0; c < 4; c++) {
                av += xn[c] * sWd[c * 32 + o];
                bv += xn[c] * sWb[c * 32 + o];
            }
            a[o] = av; b[o] = bv;
        }
        float4* Ao = (float4*)(g_A + (size_t)i * 32);
        float4* Bo = (float4*)(g_B + (size_t)i * 32);
        #pragma unroll
        for (int q = 0; q < 8; q++) {
            Ao[q] = make_float4(a[4*q], a[4*q+1], a[4*q+2], a[4*q+3]);
            Bo[q] = make_float4(b[4*q], b[4*q+1], b[4*q+2], b[4*q+3]);
        }
        ((float4*)g_sumenc)[i] = make_float4(0.f, 0.f, 0.f, 0.f);
        g_cnt[i] = 0.f;
    }
}

// ---- fill B staging tile ----
__device__ __forceinline__ void fill_B16(const float* __restrict__ W, uint4* sB) {
    for (int idx = threadIdx.x; idx < 256; idx += 128) {
        int kt = idx >> 7, nt = (idx >> 5) & 3, l = idx & 31;
        int g = l >> 2, c = l & 3;
        int col = nt * 8 + g;
        int r0 = kt * 16 + 2 * c;
        float w0 = W[(size_t)r0 * 32 + col];
        float w1 = W[(size_t)(r0 + 1) * 32 + col];
        float w2 = W[(size_t)(r0 + 8) * 32 + col];
        float w3 = W[(size_t)(r0 + 9) * 32 + col];
        u32 h0, l0, h1, l1;
        bsplit(w0, w1, h0, l0);
        bsplit(w2, w3, h1, l1);
        sB[idx] = make_uint4(h0, h1, l0, l1);
    }
}

// ---- octet gather, two half-waves of 8 LDGs (caps live regs at ~32) ----
__device__ __forceinline__ void gather32b(int s_all, int t_all, int oct, int sub,
                                          u32* sUh, u32* sUl) {
    #pragma unroll
    for (int h = 0; h < 2; h++) {
        float4 av[4], bv[4];
        #pragma unroll
        for (int p4 = 0; p4 < 4; p4++) {
            int e_sub = 4 * (h * 4 + p4) + oct;
            int s = __shfl_sync(0xffffffffu, s_all, e_sub);
            int t = __shfl_sync(0xffffffffu, t_all, e_sub);
            av[p4] = __ldg((const float4*)(g_A + (size_t)t * 32) + sub);
            bv[p4] = __ldg((const float4*)(g_B + (size_t)s * 32) + sub);
        }
        #pragma unroll
        for (int p4 = 0; p4 < 4; p4++) {
            int e_sub = 4 * (h * 4 + p4) + oct;
            float u0 = fmaxf(av[p4].x + bv[p4].x, 0.f);
            float u1 = fmaxf(av[p4].y + bv[p4].y, 0.f);
            float u2 = fmaxf(av[p4].z + bv[p4].z, 0.f);
            float u3 = fmaxf(av[p4].w + bv[p4].w, 0.f);
            u32 h01, l01, h23, l23;
            bsplit(u0, u1, h01, l01);
            bsplit(u2, u3, h23, l23);
            *(uint2*)(sUh + e_sub * 20 + sub * 2) = make_uint2(h01, h23);
            *(uint2*)(sUl + e_sub * 20 + sub * 2) = make_uint2(l01, l23);
        }
    }
}

// ---- projection MMA ----
__device__ __forceinline__ void proj_mma(const float d[4][4],
                                         const float b20[4], const float b21[4],
                                         const u32 ph[2][2], const u32 pl[2][2],
                                         float d2[4]) {
    d2[0] = d2[1] = d2[2] = d2[3] = 0.f;
    #pragma unroll
    for (int kt2 = 0; kt2 < 2; kt2++) {
        int n0 = 2 * kt2, n1 = n0 + 1;
        float m00 = fmaxf(d[n0][0] + b20[n0], 0.f);
        float m01 = fmaxf(d[n0][1] + b21[n0], 0.f);
        float m02 = fmaxf(d[n0][2] + b20[n0], 0.f);
        float m03 = fmaxf(d[n0][3] + b21[n0], 0.f);
        float m10 = fmaxf(d[n1][0] + b20[n1], 0.f);
        float m11 = fmaxf(d[n1][1] + b21[n1], 0.f);
        float m12 = fmaxf(d[n1][2] + b20[n1], 0.f);
        float m13 = fmaxf(d[n1][3] + b21[n1], 0.f);
        u32 ah[4], al[4];
        bsplit(m00, m01, ah[0], al[0]);
        bsplit(m02, m03, ah[1], al[1]);
        bsplit(m10, m11, ah[2], al[2]);
        bsplit(m12, m13, ah[3], al[3]);
        mma16(d2, ah, ph[kt2][0], ph[kt2][1]);
        mma16(d2, al, ph[kt2][0], ph[kt2][1]);
        mma16(d2, ah, pl[kt2][0], pl[kt2][1]);
    }
}

#define TPW 4   // tiles (of 32 edges) per warp

// ===================== encoder =====================
__global__ void __launch_bounds__(128, 6) k_enc(const int* __restrict__ ei,
                                                const float* __restrict__ W2,
                                                const float* __restrict__ b2,
                                                const float* __restrict__ mW,
                                                const float* __restrict__ vW, int E) {
    __shared__ __align__(16) u32 sUh[4][32 * 20];
    __shared__ __align__(16) u32 sUl[4][32 * 20];
    __shared__ __align__(16) uint4 sB[256];

    fill_B16(W2, sB);
    __syncthreads();

    int lane = threadIdx.x & 31, warp = threadIdx.x >> 5;
    int g_ = lane >> 2, c_ = lane & 3;
    int oct = lane >> 3, sub = lane & 7;

    u32 Bh[2][4][2], Bl[2][4][2];
    {
        unsigned bb = (unsigned)__cvta_generic_to_shared(sB) + (unsigned)lane * 16u;
        #pragma unroll
        for (int kt = 0; kt < 2; kt++)
            #pragma unroll
            for (int nt = 0; nt < 4; nt++)
                lds128(bb + (unsigned)(kt * 4 + nt) * 512u,
                       Bh[kt][nt][0], Bh[kt][nt][1], Bl[kt][nt][0], Bl[kt][nt][1]);
    }

    u32 ph[2][2], pl[2][2];
    #pragma unroll
    for (int kt2 = 0; kt2 < 2; kt2++) {
        int r0 = kt2 * 16 + 2 * c_;
        float p00 = 0.f, p01 = 0.f, p10 = 0.f, p11 = 0.f;
        if (g_ < 2) {
            p00 = mW[r0 * 2 + g_];       p01 = mW[(r0 + 1) * 2 + g_];
            p10 = mW[(r0 + 8) * 2 + g_]; p11 = mW[(r0 + 9) * 2 + g_];
        } else if (g_ < 4) {
            p00 = vW[r0 * 2 + g_ - 2];       p01 = vW[(r0 + 1) * 2 + g_ - 2];
            p10 = vW[(r0 + 8) * 2 + g_ - 2]; p11 = vW[(r0 + 9) * 2 + g_ - 2];
        }
        bsplit(p00, p01, ph[kt2][0], pl[kt2][0]);
        bsplit(p10, p11, ph[kt2][1], pl[kt2][1]);
    }
    float b20[4], b21[4];
    #pragma unroll
    for (int nt = 0; nt < 4; nt++) {
        b20[nt] = b2[nt * 8 + 2 * c_];
        b21[nt] = b2[nt * 8 + 2 * c_ + 1];
    }

    u32* myUh = &sUh[warp][0];
    u32* myUl = &sUl[warp][0];
    unsigned uhb = (unsigned)__cvta_generic_to_shared(myUh)
                 + (unsigned)((lane & 15) * 80 + (lane >> 4) * 16);
    unsigned ulb = (unsigned)__cvta_generic_to_shared(myUl)
                 + (unsigned)((lane & 15) * 80 + (lane >> 4) * 16);

    int tile0 = (blockIdx.x * 4 + warp) * TPW;
    #pragma unroll 1
    for (int it = 0; it < TPW; it++) {
        int tb = (tile0 + it) * 32;
        if (tb >= E) break;
        int idx = tb + lane;
        int s_all = 0, t_all = 0;
        if (idx < E) { s_all = ei[idx]; t_all = ei[E + idx]; }

        gather32b(s_all, t_all, oct, sub, myUh, myUl);
        __syncwarp();

        #pragma unroll
        for (int mt = 0; mt < 2; mt++) {
            float d[4][4];
            #pragma unroll
            for (int nt = 0; nt < 4; nt++)
                #pragma unroll
                for (int j = 0; j < 4; j++) d[nt][j] = 0.f;
            #pragma unroll
            for (int kt = 0; kt < 2; kt++) {
                u32 ah[4], al[4];
                unsigned off = (unsigned)(mt * 16 * 80 + kt * 32);
                ldmx4(ah, uhb + off);
                ldmx4(al, ulb + off);
                #pragma unroll
                for (int nt = 0; nt < 4; nt++) {
                    mma16(d[nt], ah, Bh[kt][nt][0], Bh[kt][nt][1]);
                    mma16(d[nt], al, Bh[kt][nt][0], Bh[kt][nt][1]);
                    mma16(d[nt], ah, Bl[kt][nt][0], Bl[kt][nt][1]);
                }
            }

            float d2[4];
            proj_mma(d, b20, b21, ph, pl, d2);

            float f2 = __shfl_xor_sync(0xffffffffu, d2[0], 1);
            float f3 = __shfl_xor_sync(0xffffffffu, d2[1], 1);
            float f6 = __shfl_xor_sync(0xffffffffu, d2[2], 1);
            float f7 = __shfl_xor_sync(0xffffffffu, d2[3], 1);

            int tga = __shfl_sync(0xffffffffu, t_all, mt * 16 + g_);
            int tgb = __shfl_sync(0xffffffffu, t_all, mt * 16 + 8 + g_);
            if (c_ == 0) {
                int ea = tb + mt * 16 + g_;
                int eb_ = ea + 8;
                if (ea < E) {
                    red4(g_sumenc + (size_t)tga * 4, d2[0], d2[1], f2, f3);
                    redf(&g_cnt[tga], 1.0f);
                }
                if (eb_ < E) {
                    red4(g_sumenc + (size_t)tgb * 4, d2[2], d2[3], f6, f7);
                    redf(&g_cnt[tgb], 1.0f);
                }
            }
        }
        __syncwarp();
    }
}

// ---- K4: per-node mid (also zeroes sumout) ----
__global__ void k_mid(const float* __restrict__ mb, const float* __restrict__ vb,
                      const float* __restrict__ dW1, const float* __restrict__ db1,
                      const float* __restrict__ eps2,
                      float* __restrict__ out_mu, float* __restrict__ out_lv, int n) {
    __shared__ float sWd[64], sWb[64], sdb1[32], smb[2], svb[2];
    int t = threadIdx.x;
    if (t < 32) {
        sdb1[t] = db1[t];
        sWd[t]      = dW1[t]      - dW1[64 + t];
        sWd[32 + t] = dW1[32 + t] - dW1[96 + t];
        sWb[t]      = dW1[64 + t];
        sWb[32 + t] = dW1[96 + t];
    }
    if (t < 2) { smb[t] = mb[t]; svb[t] = vb[t]; }
    __syncthreads();
    for (int i = blockIdx.x * blockDim.x + t; i < n; i += gridDim.x * blockDim.x) {
        float4 s = ((const float4*)g_sumenc)[i];
        float inv = 1.0f / fmaxf(g_cnt[i], 1.0f);
        float mu0 = s.x * inv + smb[0];
        float mu1 = s.y * inv + smb[1];
        float lv0 = s.z * inv + svb[0];
        float lv1 = s.w * inv + svb[1];
        float2 ep = ((const float2*)eps2)[i];
        float z0 = mu0 + ep.x * expf(0.5f * lv0);
        float z1 = mu1 + ep.y * expf(0.5f * lv1);
        ((float2*)out_mu)[i] = make_float2(mu0, mu1);
        ((float2*)out_lv)[i] = make_float2(lv0, lv1);
        float a[32], b[32];
        #pragma unroll
        for (int o = 0; o < 32; o++) {
            a[o] = sdb1[o] + z0 * sWd[o] + z1 * sWd[32 + o];
            b[o] = z0 * sWb[o] + z1 * sWb[32 + o];
        }
        float4* Ao = (float4*)(g_A + (size_t)i * 32);
        float4* Bo = (float4*)(g_B + (size_t)i * 32);
        #pragma unroll
        for (int q = 0; q < 8; q++) {
            Ao[q] = make_float4(a[4*q], a[4*q+1], a[4*q+2], a[4*q+3]);
            Bo[q] = make_float4(b[4*q], b[4*q+1], b[4*q+2], b[4*q+3]);
        }
        ((float4*)g_sumout)[i] = make_float4(0.f, 0.f, 0.f, 0.f);
    }
}

// ===================== decoder =====================
__global__ void __launch_bounds__(128, 6) k_dec(const int* __restrict__ ei,
                                                const float* __restrict__ W2,
                                                const float* __restrict__ b2,
                                                const float* __restrict__ W3,
                                                const float* __restrict__ b3, int E) {
    __shared__ __align__(16) u32 sUh[4][32 * 20];
    __shared__ __align__(16) u32 sUl[4][32 * 20];
    __shared__ __align__(16) uint4 sB[256];

    fill_B16(W2, sB);
    __syncthreads();

    int lane = threadIdx.x & 31, warp = threadIdx.x >> 5;
    int g_ = lane >> 2, c_ = lane & 3;
    int oct = lane >> 3, sub = lane & 7;

    u32 Bh[2][4][2], Bl[2][4][2];
    {
        unsigned bb = (unsigned)__cvta_generic_to_shared(sB) + (unsigned)lane * 16u;
        #pragma unroll
        for (int kt = 0; kt < 2; kt++)
            #pragma unroll
            for (int nt = 0; nt < 4; nt++)
                lds128(bb + (unsigned)(kt * 4 + nt) * 512u,
                       Bh[kt][nt][0], Bh[kt][nt][1], Bl[kt][nt][0], Bl[kt][nt][1]);
    }

    u32 ph[2][2], pl[2][2];
    #pragma unroll
    for (int kt2 = 0; kt2 < 2; kt2++) {
        int r0 = kt2 * 16 + 2 * c_;
        float p00 = 0.f, p01 = 0.f, p10 = 0.f, p11 = 0.f;
        if (g_ < 4) {
            p00 = W3[r0 * 4 + g_];       p01 = W3[(r0 + 1) * 4 + g_];
            p10 = W3[(r0 + 8) * 4 + g_]; p11 = W3[(r0 + 9) * 4 + g_];
        }
        bsplit(p00, p01, ph[kt2][0], pl[kt2][0]);
        bsplit(p10, p11, ph[kt2][1], pl[kt2][1]);
    }
    float b20[4], b21[4];
    #pragma unroll
    for (int nt = 0; nt < 4; nt++) {
        b20[nt] = b2[nt * 8 + 2 * c_];
        b21[nt] = b2[nt * 8 + 2 * c_ + 1];
    }
    float b30 = b3[0], b31 = b3[1], b32 = b3[2], b33 = b3[3];

    u32* myUh = &sUh[warp][0];
    u32* myUl = &sUl[warp][0];
    unsigned uhb = (unsigned)__cvta_generic_to_shared(myUh)
                 + (unsigned)((lane & 15) * 80 + (lane >> 4) * 16);
    unsigned ulb = (unsigned)__cvta_generic_to_shared(myUl)
                 + (unsigned)((lane & 15) * 80 + (lane >> 4) * 16);

    int tile0 = (blockIdx.x * 4 + warp) * TPW;
    #pragma unroll 1
    for (int it = 0; it < TPW; it++) {
        int tb = (tile0 + it) * 32;
        if (tb >= E) break;
        int idx = tb + lane;
        int s_all = 0, t_all = 0;
        if (idx < E) { s_all = ei[idx]; t_all = ei[E + idx]; }

        gather32b(s_all, t_all, oct, sub, myUh, myUl);
        __syncwarp();

        #pragma unroll
        for (int mt = 0; mt < 2; mt++) {
            float d[4][4];
            #pragma unroll
            for (int nt = 0; nt < 4; nt++)
                #pragma unroll
                for (int j = 0; j < 4; j++) d[nt][j] = 0.f;
            #pragma unroll
            for (int kt = 0; kt < 2; kt++) {
                u32 ah[4], al[4];
                unsigned off = (unsigned)(mt * 16 * 80 + kt * 32);
                ldmx4(ah, uhb + off);
                ldmx4(al, ulb + off);
                #pragma unroll
                for (int nt = 0; nt < 4; nt++) {
                    mma16(d[nt], ah, Bh[kt][nt][0], Bh[kt][nt][1]);
                    mma16(d[nt], al, Bh[kt][nt][0], Bh[kt][nt][1]);
                    mma16(d[nt], ah, Bl[kt][nt][0], Bl[kt][nt][1]);
                }
            }

            float d2[4];
            proj_mma(d, b20, b21, ph, pl, d2);

            float f2 = __shfl_xor_sync(0xffffffffu, d2[0], 1);
            float f3 = __shfl_xor_sync(0xffffffffu, d2[1], 1);
            float f6 = __shfl_xor_sync(0xffffffffu, d2[2], 1);
            float f7 = __shfl_xor_sync(0xffffffffu, d2[3], 1);

            int tga = __shfl_sync(0xffffffffu, t_all, mt * 16 + g_);
            int tgb = __shfl_sync(0xffffffffu, t_all, mt * 16 + 8 + g_);
            if (c_ == 0) {
                int ea = tb + mt * 16 + g_;
                int eb_ = ea + 8;
                if (ea < E)
                    red4(g_sumout + (size_t)tga * 4, d2[0] + b30, d2[1] + b31, f2 + b32, f3 + b33);
                if (eb_ < E)
                    red4(g_sumout + (size_t)tgb * 4, d2[2] + b30, d2[3] + b31, f6 + b32, f7 + b33);
            }
        }
        __syncwarp();
    }
}

// ---- K6: per-node output mean ----
__global__ void k_out(float* __restrict__ out, int n) {
    for (int i = blockIdx.x * blockDim.x + threadIdx.x; i < n; i += gridDim.x * blockDim.x) {
        float inv = 1.0f / fmaxf(g_cnt[i], 1.0f);
        float4 s = ((const float4*)g_sumout)[i];
        ((float4*)out)[i] = make_float4(s.x * inv, s.y * inv, s.z * inv, s.w * inv);
    }
}

extern "C" void kernel_launch(void* const* d_in, const int* in_sizes, int n_in,
                              void* d_out, int out_size) {
    const float* x     = (const float*)d_in[0];
    const int*   ei    = (const int*)d_in[1];
    const float* eps   = (const float*)d_in[2];
    const float* gamma = (const float*)d_in[3];
    const float* beta  = (const float*)d_in[4];
    const float* eW1   = (const float*)d_in[5];
    const float* eb1   = (const float*)d_in[6];
    const float* eW2   = (const float*)d_in[7];
    const float* eb2   = (const float*)d_in[8];
    const float* mW    = (const float*)d_in[9];
    const float* mb    = (const float*)d_in[10];
    const float* vW    = (const float*)d_in[11];
    const float* vb    = (const float*)d_in[12];
    const float* dW1   = (const float*)d_in[13];
    const float* db1   = (const float*)d_in[14];
    const float* dW2   = (const float*)d_in[15];
    const float* db2   = (const float*)d_in[16];
    const float* dW3   = (const float*)d_in[17];
    const float* db3   = (const float*)d_in[18];

    int n = in_sizes[0] / 4;
    int E = in_sizes[1] / 2;

    float* out    = (float*)d_out;
    float* out_mu = out + (size_t)n * 4;
    float* out_lv = out + (size_t)n * 6;

    int nb = (n + 255) / 256;
    int eb = (E + 128 * TPW - 1) / (128 * TPW);

    k_zero_s<<<1, 32>>>();
    k_stats<<<256, 256>>>((const float4*)x, n);
    k_pre<<<nb, 256>>>((const float4*)x, gamma, beta, eW1, eb1, n, 1.0f / (float)n);
    k_enc<<<eb, 128>>>(ei, eW2, eb2, mW, vW, E);
    k_mid<<<nb, 256>>>(mb, vb, dW1, db1, eps, out_mu, out_lv, n);
    k_dec<<<eb, 128>>>(ei, dW2, db2, dW3, db3, E);
    k_out<<<nb, 256>>>(out, n);
}

// round 15
// speedup vs baseline: 1.0022x; 1.0022x over previous
#include <cuda_runtime.h>
#include <math.h>

#define N_MAX 100000
typedef unsigned long long ull;
typedef unsigned int u32;

// ---- scratch ----
__device__ __align__(16) float g_A[N_MAX * 32];
__device__ __align__(16) float g_B[N_MAX * 32];
__device__ __align__(16) float g_sumenc[N_MAX * 4];
__device__ __align__(16) float g_cnt[N_MAX];
__device__ __align__(16) float g_sumout[N_MAX * 4];
__device__ __align__(16) float g_stats[8];

// ---- helpers ----
__device__ __forceinline__ void red4(float* p, float a, float b, float c, float d) {
    asm volatile("red.global.add.v4.f32 [%0], {%1,%2,%3,%4};"
                 :: "l"(p), "f"(a), "f"(b), "f"(c), "f"(d) : "memory");
}
__device__ __forceinline__ void redf(float* p, float v) {
    asm volatile("red.global.add.f32 [%0], %1;" :: "l"(p), "f"(v) : "memory");
}
__device__ __forceinline__ u32 bfpack(float y, float x) {
    u32 r; asm("cvt.rn.bf16x2.f32 %0, %1, %2;" : "=r"(r) : "f"(y), "f"(x)); return r;
}
__device__ __forceinline__ void bsplit(float x, float y, u32& h, u32& l) {
    h = bfpack(y, x);
    float xr = x - __uint_as_float(h << 16);
    float yr = y - __uint_as_float(h & 0xFFFF0000u);
    l = bfpack(yr, xr);
}
__device__ __forceinline__ void mma16(float* d, const u32* a, u32 b0, u32 b1) {
    asm volatile("mma.sync.aligned.m16n8k16.row.col.f32.bf16.bf16.f32 "
                 "{%0,%1,%2,%3},{%4,%5,%6,%7},{%8,%9},{%0,%1,%2,%3};"
                 : "+f"(d[0]), "+f"(d[1]), "+f"(d[2]), "+f"(d[3])
                 : "r"(a[0]), "r"(a[1]), "r"(a[2]), "r"(a[3]), "r"(b0), "r"(b1));
}
__device__ __forceinline__ void lds128(unsigned addr, u32& a, u32& b, u32& c, u32& d) {
    asm volatile("ld.shared.v4.u32 {%0,%1,%2,%3}, [%4];"
                 : "=r"(a), "=r"(b), "=r"(c), "=r"(d) : "r"(addr));
}
__device__ __forceinline__ void ldmx4(u32* r, unsigned addr) {
    asm volatile("ldmatrix.sync.aligned.m8n8.x4.shared.b16 {%0,%1,%2,%3}, [%4];"
                 : "=r"(r[0]), "=r"(r[1]), "=r"(r[2]), "=r"(r[3]) : "r"(addr));
}

// ---- K0: zero stats only ----
__global__ void k_zero_s() {
    if (threadIdx.x < 8) g_stats[threadIdx.x] = 0.f;
}

// ---- K1: batchnorm statistics ----
__global__ void k_stats(const float4* __restrict__ x, int n) {
    float sx = 0, sy = 0, sz = 0, sw = 0, qx = 0, qy = 0, qz = 0, qw = 0;
    for (int i = blockIdx.x * blockDim.x + threadIdx.x; i < n; i += gridDim.x * blockDim.x) {
        float4 v = x[i];
        sx += v.x; sy += v.y; sz += v.z; sw += v.w;
        qx += v.x * v.x; qy += v.y * v.y; qz += v.z * v.z; qw += v.w * v.w;
    }
    #pragma unroll
    for (int off = 16; off; off >>= 1) {
        sx += __shfl_down_sync(0xffffffffu, sx, off);
        sy += __shfl_down_sync(0xffffffffu, sy, off);
        sz += __shfl_down_sync(0xffffffffu, sz, off);
        sw += __shfl_down_sync(0xffffffffu, sw, off);
        qx += __shfl_down_sync(0xffffffffu, qx, off);
        qy += __shfl_down_sync(0xffffffffu, qy, off);
        qz += __shfl_down_sync(0xffffffffu, qz, off);
        qw += __shfl_down_sync(0xffffffffu, qw, off);
    }
    if ((threadIdx.x & 31) == 0) {
        atomicAdd(&g_stats[0], sx); atomicAdd(&g_stats[1], sy);
        atomicAdd(&g_stats[2], sz); atomicAdd(&g_stats[3], sw);
        atomicAdd(&g_stats[4], qx); atomicAdd(&g_stats[5], qy);
        atomicAdd(&g_stats[6], qz); atomicAdd(&g_stats[7], qw);
    }
}

// ---- K2: BN + encoder layer-1 split (also zeroes sumenc/cnt) ----
__global__ void k_pre(const float4* __restrict__ x,
                      const float* __restrict__ gamma, const float* __restrict__ beta,
                      const float* __restrict__ eW1, const float* __restrict__ eb1,
                      int n, float invN) {
    __shared__ float sWd[128], sWb[128], sb1[32], sScale[4], sShift[4];
    int t = threadIdx.x;
    if (t < 128) {
        int c = t >> 5, o = t & 31;
        float wa = eW1[c * 32 + o], wb = eW1[(4 + c) * 32 + o];
        sWd[t] = wa - wb; sWb[t] = wb;
    }
    if (t < 32) sb1[t] = eb1[t];
    if (t < 4) {
        float m = g_stats[t] * invN;
        float v = g_stats[4 + t] * invN - m * m;
        float s = rsqrtf(v + 1e-5f) * gamma[t];
        sScale[t] = s; sShift[t] = beta[t] - m * s;
    }
    __syncthreads();
    for (int i = blockIdx.x * blockDim.x + t; i < n; i += gridDim.x * blockDim.x) {
        float4 xv = x[i];
        float xn[4];
        xn[0] = xv.x * sScale[0] + sShift[0];
        xn[1] = xv.y * sScale[1] + sShift[1];
        xn[2] = xv.z * sScale[2] + sShift[2];
        xn[3] = xv.w * sScale[3] + sShift[3];
        float a[32], b[32];
        #pragma unroll
        for (int o = 0; o < 32; o++) {
            float av = sb1[o], bv = 0.f;
            #pragma unroll
            for (int c = 0; c < 4; c++) {
                av += xn[c] * sWd[c * 32 + o];
                bv += xn[c] * sWb[c * 32 + o];
            }
            a[o] = av; b[o] = bv;
        }
        float4* Ao = (float4*)(g_A + (size_t)i * 32);
        float4* Bo = (float4*)(g_B + (size_t)i * 32);
        #pragma unroll
        for (int q = 0; q < 8; q++) {
            Ao[q] = make_float4(a[4*q], a[4*q+1], a[4*q+2], a[4*q+3]);
            Bo[q] = make_float4(b[4*q], b[4*q+1], b[4*q+2], b[4*q+3]);
        }
        ((float4*)g_sumenc)[i] = make_float4(0.f, 0.f, 0.f, 0.f);
        g_cnt[i] = 0.f;
    }
}

// ---- fill B staging tile ----
__device__ __forceinline__ void fill_B16(const float* __restrict__ W, uint4* sB) {
    for (int idx = threadIdx.x; idx < 256; idx += 128) {
        int kt = idx >> 7, nt = (idx >> 5) & 3, l = idx & 31;
        int g = l >> 2, c = l & 3;
        int col = nt * 8 + g;
        int r0 = kt * 16 + 2 * c;
        float w0 = W[(size_t)r0 * 32 + col];
        float w1 = W[(size_t)(r0 + 1) * 32 + col];
        float w2 = W[(size_t)(r0 + 8) * 32 + col];
        float w3 = W[(size_t)(r0 + 9) * 32 + col];
        u32 h0, l0, h1, l1;
        bsplit(w0, w1, h0, l0);
        bsplit(w2, w3, h1, l1);
        sB[idx] = make_uint4(h0, h1, l0, l1);
    }
}

// ---- octet gather, full MLP (16 outstanding LDGs), bf16 split into uh/ul ----
__device__ __forceinline__ void gather32b(int s_all, int t_all, int oct, int sub,
                                          u32* sUh, u32* sUl) {
    #pragma unroll
    for (int p = 0; p < 8; p++) {
        int e_sub = 4 * p + oct;
        int s = __shfl_sync(0xffffffffu, s_all, e_sub);
        int t = __shfl_sync(0xffffffffu, t_all, e_sub);
        float4 a = __ldg((const float4*)(g_A + (size_t)t * 32) + sub);
        float4 b = __ldg((const float4*)(g_B + (size_t)s * 32) + sub);
        float u0 = fmaxf(a.x + b.x, 0.f);
        float u1 = fmaxf(a.y + b.y, 0.f);
        float u2 = fmaxf(a.z + b.z, 0.f);
        float u3 = fmaxf(a.w + b.w, 0.f);
        u32 h01, l01, h23, l23;
        bsplit(u0, u1, h01, l01);
        bsplit(u2, u3, h23, l23);
        *(uint2*)(sUh + e_sub * 20 + sub * 2) = make_uint2(h01, h23);
        *(uint2*)(sUl + e_sub * 20 + sub * 2) = make_uint2(l01, l23);
    }
}

// ---- projection MMA ----
__device__ __forceinline__ void proj_mma(const float d[4][4],
                                         const float b20[4], const float b21[4],
                                         const u32 ph[2][2], const u32 pl[2][2],
                                         float d2[4]) {
    d2[0] = d2[1] = d2[2] = d2[3] = 0.f;
    #pragma unroll
    for (int kt2 = 0; kt2 < 2; kt2++) {
        int n0 = 2 * kt2, n1 = n0 + 1;
        float m00 = fmaxf(d[n0][0] + b20[n0], 0.f);
        float m01 = fmaxf(d[n0][1] + b21[n0], 0.f);
        float m02 = fmaxf(d[n0][2] + b20[n0], 0.f);
        float m03 = fmaxf(d[n0][3] + b21[n0], 0.f);
        float m10 = fmaxf(d[n1][0] + b20[n1], 0.f);
        float m11 = fmaxf(d[n1][1] + b21[n1], 0.f);
        float m12 = fmaxf(d[n1][2] + b20[n1], 0.f);
        float m13 = fmaxf(d[n1][3] + b21[n1], 0.f);
        u32 ah[4], al[4];
        bsplit(m00, m01, ah[0], al[0]);
        bsplit(m02, m03, ah[1], al[1]);
        bsplit(m10, m11, ah[2], al[2]);
        bsplit(m12, m13, ah[3], al[3]);
        mma16(d2, ah, ph[kt2][0], ph[kt2][1]);
        mma16(d2, al, ph[kt2][0], ph[kt2][1]);
        mma16(d2, ah, pl[kt2][0], pl[kt2][1]);
    }
}

#define TPW 8   // tiles (of 32 edges) per warp

// ===================== encoder =====================
__global__ void __launch_bounds__(128, 5) k_enc(const int* __restrict__ ei,
                                                const float* __restrict__ W2,
                                                const float* __restrict__ b2,
                                                const float* __restrict__ mW,
                                                const float* __restrict__ vW, int E) {
    __shared__ __align__(16) u32 sUh[4][32 * 20];
    __shared__ __align__(16) u32 sUl[4][32 * 20];
    __shared__ __align__(16) uint4 sB[256];

    fill_B16(W2, sB);
    __syncthreads();

    int lane = threadIdx.x & 31, warp = threadIdx.x >> 5;
    int g_ = lane >> 2, c_ = lane & 3;
    int oct = lane >> 3, sub = lane & 7;

    u32 Bh[2][4][2], Bl[2][4][2];
    {
        unsigned bb = (unsigned)__cvta_generic_to_shared(sB) + (unsigned)lane * 16u;
        #pragma unroll
        for (int kt = 0; kt < 2; kt++)
            #pragma unroll
            for (int nt = 0; nt < 4; nt++)
                lds128(bb + (unsigned)(kt * 4 + nt) * 512u,
                       Bh[kt][nt][0], Bh[kt][nt][1], Bl[kt][nt][0], Bl[kt][nt][1]);
    }

    u32 ph[2][2], pl[2][2];
    #pragma unroll
    for (int kt2 = 0; kt2 < 2; kt2++) {
        int r0 = kt2 * 16 + 2 * c_;
        float p00 = 0.f, p01 = 0.f, p10 = 0.f, p11 = 0.f;
        if (g_ < 2) {
            p00 = mW[r0 * 2 + g_];       p01 = mW[(r0 + 1) * 2 + g_];
            p10 = mW[(r0 + 8) * 2 + g_]; p11 = mW[(r0 + 9) * 2 + g_];
        } else if (g_ < 4) {
            p00 = vW[r0 * 2 + g_ - 2];       p01 = vW[(r0 + 1) * 2 + g_ - 2];
            p10 = vW[(r0 + 8) * 2 + g_ - 2]; p11 = vW[(r0 + 9) * 2 + g_ - 2];
        }
        bsplit(p00, p01, ph[kt2][0], pl[kt2][0]);
        bsplit(p10, p11, ph[kt2][1], pl[kt2][1]);
    }
    float b20[4], b21[4];
    #pragma unroll
    for (int nt = 0; nt < 4; nt++) {
        b20[nt] = b2[nt * 8 + 2 * c_];
        b21[nt] = b2[nt * 8 + 2 * c_ + 1];
    }

    u32* myUh = &sUh[warp][0];
    u32* myUl = &sUl[warp][0];
    unsigned uhb = (unsigned)__cvta_generic_to_shared(myUh)
                 + (unsigned)((lane & 15) * 80 + (lane >> 4) * 16);
    unsigned ulb = (unsigned)__cvta_generic_to_shared(myUl)
                 + (unsigned)((lane & 15) * 80 + (lane >> 4) * 16);

    int tile0 = (blockIdx.x * 4 + warp) * TPW;
    #pragma unroll 1
    for (int it = 0; it < TPW; it++) {
        int tb = (tile0 + it) * 32;
        if (tb >= E) break;
        int idx = tb + lane;
        int s_all = 0, t_all = 0;
        if (idx < E) { s_all = ei[idx]; t_all = ei[E + idx]; }

        gather32b(s_all, t_all, oct, sub, myUh, myUl);
        __syncwarp();

        #pragma unroll
        for (int mt = 0; mt < 2; mt++) {
            float d[4][4];
            #pragma unroll
            for (int nt = 0; nt < 4; nt++)
                #pragma unroll
                for (int j = 0; j < 4; j++) d[nt][j] = 0.f;
            #pragma unroll
            for (int kt = 0; kt < 2; kt++) {
                u32 ah[4], al[4];
                unsigned off = (unsigned)(mt * 16 * 80 + kt * 32);
                ldmx4(ah, uhb + off);
                ldmx4(al, ulb + off);
                #pragma unroll
                for (int nt = 0; nt < 4; nt++) {
                    mma16(d[nt], ah, Bh[kt][nt][0], Bh[kt][nt][1]);
                    mma16(d[nt], al, Bh[kt][nt][0], Bh[kt][nt][1]);
                    mma16(d[nt], ah, Bl[kt][nt][0], Bl[kt][nt][1]);
                }
            }

            float d2[4];
            proj_mma(d, b20, b21, ph, pl, d2);

            float f2 = __shfl_xor_sync(0xffffffffu, d2[0], 1);
            float f3 = __shfl_xor_sync(0xffffffffu, d2[1], 1);
            float f6 = __shfl_xor_sync(0xffffffffu, d2[2], 1);
            float f7 = __shfl_xor_sync(0xffffffffu, d2[3], 1);

            int tga = __shfl_sync(0xffffffffu, t_all, mt * 16 + g_);
            int tgb = __shfl_sync(0xffffffffu, t_all, mt * 16 + 8 + g_);
            if (c_ == 0) {
                int ea = tb + mt * 16 + g_;
                int eb_ = ea + 8;
                if (ea < E) {
                    red4(g_sumenc + (size_t)tga * 4, d2[0], d2[1], f2, f3);
                    redf(&g_cnt[tga], 1.0f);
                }
                if (eb_ < E) {
                    red4(g_sumenc + (size_t)tgb * 4, d2[2], d2[3], f6, f7);
                    redf(&g_cnt[tgb], 1.0f);
                }
            }
        }
        __syncwarp();
    }
}

// ---- K4: per-node mid (also zeroes sumout) ----
__global__ void k_mid(const float* __restrict__ mb, const float* __restrict__ vb,
                      const float* __restrict__ dW1, const float* __restrict__ db1,
                      const float* __restrict__ eps2,
                      float* __restrict__ out_mu, float* __restrict__ out_lv, int n) {
    __shared__ float sWd[64], sWb[64], sdb1[32], smb[2], svb[2];
    int t = threadIdx.x;
    if (t < 32) {
        sdb1[t] = db1[t];
        sWd[t]      = dW1[t]      - dW1[64 + t];
        sWd[32 + t] = dW1[32 + t] - dW1[96 + t];
        sWb[t]      = dW1[64 + t];
        sWb[32 + t] = dW1[96 + t];
    }
    if (t < 2) { smb[t] = mb[t]; svb[t] = vb[t]; }
    __syncthreads();
    for (int i = blockIdx.x * blockDim.x + t; i < n; i += gridDim.x * blockDim.x) {
        float4 s = ((const float4*)g_sumenc)[i];
        float inv = 1.0f / fmaxf(g_cnt[i], 1.0f);
        float mu0 = s.x * inv + smb[0];
        float mu1 = s.y * inv + smb[1];
        float lv0 = s.z * inv + svb[0];
        float lv1 = s.w * inv + svb[1];
        float2 ep = ((const float2*)eps2)[i];
        float z0 = mu0 + ep.x * expf(0.5f * lv0);
        float z1 = mu1 + ep.y * expf(0.5f * lv1);
        ((float2*)out_mu)[i] = make_float2(mu0, mu1);
        ((float2*)out_lv)[i] = make_float2(lv0, lv1);
        float a[32], b[32];
        #pragma unroll
        for (int o = 0; o < 32; o++) {
            a[o] = sdb1[o] + z0 * sWd[o] + z1 * sWd[32 + o];
            b[o] = z0 * sWb[o] + z1 * sWb[32 + o];
        }
        float4* Ao = (float4*)(g_A + (size_t)i * 32);
        float4* Bo = (float4*)(g_B + (size_t)i * 32);
        #pragma unroll
        for (int q = 0; q < 8; q++) {
            Ao[q] = make_float4(a[4*q], a[4*q+1], a[4*q+2], a[4*q+3]);
            Bo[q] = make_float4(b[4*q], b[4*q+1], b[4*q+2], b[4*q+3]);
        }
        ((float4*)g_sumout)[i] = make_float4(0.f, 0.f, 0.f, 0.f);
    }
}

// ===================== decoder =====================
__global__ void __launch_bounds__(128, 5) k_dec(const int* __restrict__ ei,
                                                const float* __restrict__ W2,
                                                const float* __restrict__ b2,
                                                const float* __restrict__ W3,
                                                const float* __restrict__ b3, int E) {
    __shared__ __align__(16) u32 sUh[4][32 * 20];
    __shared__ __align__(16) u32 sUl[4][32 * 20];
    __shared__ __align__(16) uint4 sB[256];

    fill_B16(W2, sB);
    __syncthreads();

    int lane = threadIdx.x & 31, warp = threadIdx.x >> 5;
    int g_ = lane >> 2, c_ = lane & 3;
    int oct = lane >> 3, sub = lane & 7;

    u32 Bh[2][4][2], Bl[2][4][2];
    {
        unsigned bb = (unsigned)__cvta_generic_to_shared(sB) + (unsigned)lane * 16u;
        #pragma unroll
        for (int kt = 0; kt < 2; kt++)
            #pragma unroll
            for (int nt = 0; nt < 4; nt++)
                lds128(bb + (unsigned)(kt * 4 + nt) * 512u,
                       Bh[kt][nt][0], Bh[kt][nt][1], Bl[kt][nt][0], Bl[kt][nt][1]);
    }

    u32 ph[2][2], pl[2][2];
    #pragma unroll
    for (int kt2 = 0; kt2 < 2; kt2++) {
        int r0 = kt2 * 16 + 2 * c_;
        float p00 = 0.f, p01 = 0.f, p10 = 0.f, p11 = 0.f;
        if (g_ < 4) {
            p00 = W3[r0 * 4 + g_];       p01 = W3[(r0 + 1) * 4 + g_];
            p10 = W3[(r0 + 8) * 4 + g_]; p11 = W3[(r0 + 9) * 4 + g_];
        }
        bsplit(p00, p01, ph[kt2][0], pl[kt2][0]);
        bsplit(p10, p11, ph[kt2][1], pl[kt2][1]);
    }
    float b20[4], b21[4];
    #pragma unroll
    for (int nt = 0; nt < 4; nt++) {
        b20[nt] = b2[nt * 8 + 2 * c_];
        b21[nt] = b2[nt * 8 + 2 * c_ + 1];
    }
    float b30 = b3[0], b31 = b3[1], b32 = b3[2], b33 = b3[3];

    u32* myUh = &sUh[warp][0];
    u32* myUl = &sUl[warp][0];
    unsigned uhb = (unsigned)__cvta_generic_to_shared(myUh)
                 + (unsigned)((lane & 15) * 80 + (lane >> 4) * 16);
    unsigned ulb = (unsigned)__cvta_generic_to_shared(myUl)
                 + (unsigned)((lane & 15) * 80 + (lane >> 4) * 16);

    int tile0 = (blockIdx.x * 4 + warp) * TPW;
    #pragma unroll 1
    for (int it = 0; it < TPW; it++) {
        int tb = (tile0 + it) * 32;
        if (tb >= E) break;
        int idx = tb + lane;
        int s_all = 0, t_all = 0;
        if (idx < E) { s_all = ei[idx]; t_all = ei[E + idx]; }

        gather32b(s_all, t_all, oct, sub, myUh, myUl);
        __syncwarp();

        #pragma unroll
        for (int mt = 0; mt < 2; mt++) {
            float d[4][4];
            #pragma unroll
            for (int nt = 0; nt < 4; nt++)
                #pragma unroll
                for (int j = 0; j < 4; j++) d[nt][j] = 0.f;
            #pragma unroll
            for (int kt = 0; kt < 2; kt++) {
                u32 ah[4], al[4];
                unsigned off = (unsigned)(mt * 16 * 80 + kt * 32);
                ldmx4(ah, uhb + off);
                ldmx4(al, ulb + off);
                #pragma unroll
                for (int nt = 0; nt < 4; nt++) {
                    mma16(d[nt], ah, Bh[kt][nt][0], Bh[kt][nt][1]);
                    mma16(d[nt], al, Bh[kt][nt][0], Bh[kt][nt][1]);
                    mma16(d[nt], ah, Bl[kt][nt][0], Bl[kt][nt][1]);
                }
            }

            float d2[4];
            proj_mma(d, b20, b21, ph, pl, d2);

            float f2 = __shfl_xor_sync(0xffffffffu, d2[0], 1);
            float f3 = __shfl_xor_sync(0xffffffffu, d2[1], 1);
            float f6 = __shfl_xor_sync(0xffffffffu, d2[2], 1);
            float f7 = __shfl_xor_sync(0xffffffffu, d2[3], 1);

            int tga = __shfl_sync(0xffffffffu, t_all, mt * 16 + g_);
            int tgb = __shfl_sync(0xffffffffu, t_all, mt * 16 + 8 + g_);
            if (c_ == 0) {
                int ea = tb + mt * 16 + g_;
                int eb_ = ea + 8;
                if (ea < E)
                    red4(g_sumout + (size_t)tga * 4, d2[0] + b30, d2[1] + b31, f2 + b32, f3 + b33);
                if (eb_ < E)
                    red4(g_sumout + (size_t)tgb * 4, d2[2] + b30, d2[3] + b31, f6 + b32, f7 + b33);
            }
        }
        __syncwarp();
    }
}

// ---- K6: per-node output mean ----
__global__ void k_out(float* __restrict__ out, int n) {
    for (int i = blockIdx.x * blockDim.x + threadIdx.x; i < n; i += gridDim.x * blockDim.x) {
        float inv = 1.0f / fmaxf(g_cnt[i], 1.0f);
        float4 s = ((const float4*)g_sumout)[i];
        ((float4*)out)[i] = make_float4(s.x * inv, s.y * inv, s.z * inv, s.w * inv);
    }
}

extern "C" void kernel_launch(void* const* d_in, const int* in_sizes, int n_in,
                              void* d_out, int out_size) {
    const float* x     = (const float*)d_in[0];
    const int*   ei    = (const int*)d_in[1];
    const float* eps   = (const float*)d_in[2];
    const float* gamma = (const float*)d_in[3];
    const float* beta  = (const float*)d_in[4];
    const float* eW1   = (const float*)d_in[5];
    const float* eb1   = (const float*)d_in[6];
    const float* eW2   = (const float*)d_in[7];
    const float* eb2   = (const float*)d_in[8];
    const float* mW    = (const float*)d_in[9];
    const float* mb    = (const float*)d_in[10];
    const float* vW    = (const float*)d_in[11];
    const float* vb    = (const float*)d_in[12];
    const float* dW1   = (const float*)d_in[13];
    const float* db1   = (const float*)d_in[14];
    const float* dW2   = (const float*)d_in[15];
    const float* db2   = (const float*)d_in[16];
    const float* dW3   = (const float*)d_in[17];
    const float* db3   = (const float*)d_in[18];

    int n = in_sizes[0] / 4;
    int E = in_sizes[1] / 2;

    float* out    = (float*)d_out;
    float* out_mu = out + (size_t)n * 4;
    float* out_lv = out + (size_t)n * 6;

    int nb = (n + 255) / 256;
    int eb = (E + 128 * TPW - 1) / (128 * TPW);

    k_zero_s<<<1, 32>>>();
    k_stats<<<256, 256>>>((const float4*)x, n);
    k_pre<<<nb, 256>>>((const float4*)x, gamma, beta, eW1, eb1, n, 1.0f / (float)n);
    k_enc<<<eb, 128>>>(ei, eW2, eb2, mW, vW, E);
    k_mid<<<nb, 256>>>(mb, vb, dW1, db1, eps, out_mu, out_lv, n);
    k_dec<<<eb, 128>>>(ei, dW2, db2, dW3, db3, E);
    k_out<<<nb, 256>>>(out, n);
}

// round 16
// speedup vs baseline: 1.0360x; 1.0338x over previous
#include <cuda_runtime.h>
#include <math.h>

#define N_MAX 100000
typedef unsigned long long ull;
typedef unsigned int u32;

// ---- scratch ----
__device__ __align__(16) float g_A[N_MAX * 32];
__device__ __align__(16) float g_B[N_MAX * 32];
__device__ __align__(16) float g_sumenc[N_MAX * 4];
__device__ __align__(16) float g_cnt[N_MAX];
__device__ __align__(16) float g_sumout[N_MAX * 4];
__device__ __align__(16) float g_stats[8];

// ---- helpers ----
__device__ __forceinline__ void red4(float* p, float a, float b, float c, float d) {
    asm volatile("red.global.add.v4.f32 [%0], {%1,%2,%3,%4};"
                 :: "l"(p), "f"(a), "f"(b), "f"(c), "f"(d) : "memory");
}
__device__ __forceinline__ void redf(float* p, float v) {
    asm volatile("red.global.add.f32 [%0], %1;" :: "l"(p), "f"(v) : "memory");
}
__device__ __forceinline__ u32 bfpack(float y, float x) {
    u32 r; asm("cvt.rn.bf16x2.f32 %0, %1, %2;" : "=r"(r) : "f"(y), "f"(x)); return r;
}
__device__ __forceinline__ void bsplit(float x, float y, u32& h, u32& l) {
    h = bfpack(y, x);
    float xr = x - __uint_as_float(h << 16);
    float yr = y - __uint_as_float(h & 0xFFFF0000u);
    l = bfpack(yr, xr);
}
__device__ __forceinline__ void mma16(float* d, const u32* a, u32 b0, u32 b1) {
    asm volatile("mma.sync.aligned.m16n8k16.row.col.f32.bf16.bf16.f32 "
                 "{%0,%1,%2,%3},{%4,%5,%6,%7},{%8,%9},{%0,%1,%2,%3};"
                 : "+f"(d[0]), "+f"(d[1]), "+f"(d[2]), "+f"(d[3])
                 : "r"(a[0]), "r"(a[1]), "r"(a[2]), "r"(a[3]), "r"(b0), "r"(b1));
}
__device__ __forceinline__ void lds128(unsigned addr, u32& a, u32& b, u32& c, u32& d) {
    asm volatile("ld.shared.v4.u32 {%0,%1,%2,%3}, [%4];"
                 : "=r"(a), "=r"(b), "=r"(c), "=r"(d) : "r"(addr));
}
__device__ __forceinline__ void ldmx4(u32* r, unsigned addr) {
    asm volatile("ldmatrix.sync.aligned.m8n8.x4.shared.b16 {%0,%1,%2,%3}, [%4];"
                 : "=r"(r[0]), "=r"(r[1]), "=r"(r[2]), "=r"(r[3]) : "r"(addr));
}

// ---- K0: zero stats only ----
__global__ void k_zero_s() {
    if (threadIdx.x < 8) g_stats[threadIdx.x] = 0.f;
}

// ---- K1: batchnorm statistics ----
__global__ void k_stats(const float4* __restrict__ x, int n) {
    float sx = 0, sy = 0, sz = 0, sw = 0, qx = 0, qy = 0, qz = 0, qw = 0;
    for (int i = blockIdx.x * blockDim.x + threadIdx.x; i < n; i += gridDim.x * blockDim.x) {
        float4 v = x[i];
        sx += v.x; sy += v.y; sz += v.z; sw += v.w;
        qx += v.x * v.x; qy += v.y * v.y; qz += v.z * v.z; qw += v.w * v.w;
    }
    #pragma unroll
    for (int off = 16; off; off >>= 1) {
        sx += __shfl_down_sync(0xffffffffu, sx, off);
        sy += __shfl_down_sync(0xffffffffu, sy, off);
        sz += __shfl_down_sync(0xffffffffu, sz, off);
        sw += __shfl_down_sync(0xffffffffu, sw, off);
        qx += __shfl_down_sync(0xffffffffu, qx, off);
        qy += __shfl_down_sync(0xffffffffu, qy, off);
        qz += __shfl_down_sync(0xffffffffu, qz, off);
        qw += __shfl_down_sync(0xffffffffu, qw, off);
    }
    if ((threadIdx.x & 31) == 0) {
        atomicAdd(&g_stats[0], sx); atomicAdd(&g_stats[1], sy);
        atomicAdd(&g_stats[2], sz); atomicAdd(&g_stats[3], sw);
        atomicAdd(&g_stats[4], qx); atomicAdd(&g_stats[5], qy);
        atomicAdd(&g_stats[6], qz); atomicAdd(&g_stats[7], qw);
    }
}

// ---- K2: BN + encoder layer-1 split (also zeroes sumenc/cnt) ----
__global__ void k_pre(const float4* __restrict__ x,
                      const float* __restrict__ gamma, const float* __restrict__ beta,
                      const float* __restrict__ eW1, const float* __restrict__ eb1,
                      int n, float invN) {
    __shared__ float sWd[128], sWb[128], sb1[32], sScale[4], sShift[4];
    int t = threadIdx.x;
    if (t < 128) {
        int c = t >> 5, o = t & 31;
        float wa = eW1[c * 32 + o], wb = eW1[(4 + c) * 32 + o];
        sWd[t] = wa - wb; sWb[t] = wb;
    }
    if (t < 32) sb1[t] = eb1[t];
    if (t < 4) {
        float m = g_stats[t] * invN;
        float v = g_stats[4 + t] * invN - m * m;
        float s = rsqrtf(v + 1e-5f) * gamma[t];
        sScale[t] = s; sShift[t] = beta[t] - m * s;
    }
    __syncthreads();
    for (int i = blockIdx.x * blockDim.x + t; i < n; i += gridDim.x * blockDim.x) {
        float4 xv = x[i];
        float xn[4];
        xn[0] = xv.x * sScale[0] + sShift[0];
        xn[1] = xv.y * sScale[1] + sShift[1];
        xn[2] = xv.z * sScale[2] + sShift[2];
        xn[3] = xv.w * sScale[3] + sShift[3];
        float a[32], b[32];
        #pragma unroll
        for (int o = 0; o < 32; o++) {
            float av = sb1[o], bv = 0.f;
            #pragma unroll
            for (int c = 0; c < 4; c++) {
                av += xn[c] * sWd[c * 32 + o];
                bv += xn[c] * sWb[c * 32 + o];
            }
            a[o] = av; b[o] = bv;
        }
        float4* Ao = (float4*)(g_A + (size_t)i * 32);
        float4* Bo = (float4*)(g_B + (size_t)i * 32);
        #pragma unroll
        for (int q = 0; q < 8; q++) {
            Ao[q] = make_float4(a[4*q], a[4*q+1], a[4*q+2], a[4*q+3]);
            Bo[q] = make_float4(b[4*q], b[4*q+1], b[4*q+2], b[4*q+3]);
        }
        ((float4*)g_sumenc)[i] = make_float4(0.f, 0.f, 0.f, 0.f);
        g_cnt[i] = 0.f;
    }
}

// ---- fill B staging tile ----
__device__ __forceinline__ void fill_B16(const float* __restrict__ W, uint4* sB) {
    for (int idx = threadIdx.x; idx < 256; idx += 128) {
        int kt = idx >> 7, nt = (idx >> 5) & 3, l = idx & 31;
        int g = l >> 2, c = l & 3;
        int col = nt * 8 + g;
        int r0 = kt * 16 + 2 * c;
        float w0 = W[(size_t)r0 * 32 + col];
        float w1 = W[(size_t)(r0 + 1) * 32 + col];
        float w2 = W[(size_t)(r0 + 8) * 32 + col];
        float w3 = W[(size_t)(r0 + 9) * 32 + col];
        u32 h0, l0, h1, l1;
        bsplit(w0, w1, h0, l0);
        bsplit(w2, w3, h1, l1);
        sB[idx] = make_uint4(h0, h1, l0, l1);
    }
}

// ---- octet gather, full MLP (16 outstanding LDGs), bf16 split into uh/ul ----
__device__ __forceinline__ void gather32b(int s_all, int t_all, int oct, int sub,
                                          u32* sUh, u32* sUl) {
    #pragma unroll
    for (int p = 0; p < 8; p++) {
        int e_sub = 4 * p + oct;
        int s = __shfl_sync(0xffffffffu, s_all, e_sub);
        int t = __shfl_sync(0xffffffffu, t_all, e_sub);
        float4 a = __ldg((const float4*)(g_A + (size_t)t * 32) + sub);
        float4 b = __ldg((const float4*)(g_B + (size_t)s * 32) + sub);
        float u0 = fmaxf(a.x + b.x, 0.f);
        float u1 = fmaxf(a.y + b.y, 0.f);
        float u2 = fmaxf(a.z + b.z, 0.f);
        float u3 = fmaxf(a.w + b.w, 0.f);
        u32 h01, l01, h23, l23;
        bsplit(u0, u1, h01, l01);
        bsplit(u2, u3, h23, l23);
        *(uint2*)(sUh + e_sub * 20 + sub * 2) = make_uint2(h01, h23);
        *(uint2*)(sUl + e_sub * 20 + sub * 2) = make_uint2(l01, l23);
    }
}

// ---- projection MMA ----
__device__ __forceinline__ void proj_mma(const float d[4][4],
                                         const float b20[4], const float b21[4],
                                         const u32 ph[2][2], const u32 pl[2][2],
                                         float d2[4]) {
    d2[0] = d2[1] = d2[2] = d2[3] = 0.f;
    #pragma unroll
    for (int kt2 = 0; kt2 < 2; kt2++) {
        int n0 = 2 * kt2, n1 = n0 + 1;
        float m00 = fmaxf(d[n0][0] + b20[n0], 0.f);
        float m01 = fmaxf(d[n0][1] + b21[n0], 0.f);
        float m02 = fmaxf(d[n0][2] + b20[n0], 0.f);
        float m03 = fmaxf(d[n0][3] + b21[n0], 0.f);
        float m10 = fmaxf(d[n1][0] + b20[n1], 0.f);
        float m11 = fmaxf(d[n1][1] + b21[n1], 0.f);
        float m12 = fmaxf(d[n1][2] + b20[n1], 0.f);
        float m13 = fmaxf(d[n1][3] + b21[n1], 0.f);
        u32 ah[4], al[4];
        bsplit(m00, m01, ah[0], al[0]);
        bsplit(m02, m03, ah[1], al[1]);
        bsplit(m10, m11, ah[2], al[2]);
        bsplit(m12, m13, ah[3], al[3]);
        mma16(d2, ah, ph[kt2][0], ph[kt2][1]);
        mma16(d2, al, ph[kt2][0], ph[kt2][1]);
        mma16(d2, ah, pl[kt2][0], pl[kt2][1]);
    }
}

#define TPW 4   // tiles (of 32 edges) per warp

// ===================== encoder =====================
__global__ void __launch_bounds__(128, 5) k_enc(const int* __restrict__ ei,
                                                const float* __restrict__ W2,
                                                const float* __restrict__ b2,
                                                const float* __restrict__ mW,
                                                const float* __restrict__ vW, int E) {
    __shared__ __align__(16) u32 sUh[4][32 * 20];
    __shared__ __align__(16) u32 sUl[4][32 * 20];
    __shared__ __align__(16) uint4 sB[256];

    fill_B16(W2, sB);
    __syncthreads();

    int lane = threadIdx.x & 31, warp = threadIdx.x >> 5;
    int g_ = lane >> 2, c_ = lane & 3;
    int oct = lane >> 3, sub = lane & 7;

    u32 Bh[2][4][2], Bl[2][4][2];
    {
        unsigned bb = (unsigned)__cvta_generic_to_shared(sB) + (unsigned)lane * 16u;
        #pragma unroll
        for (int kt = 0; kt < 2; kt++)
            #pragma unroll
            for (int nt = 0; nt < 4; nt++)
                lds128(bb + (unsigned)(kt * 4 + nt) * 512u,
                       Bh[kt][nt][0], Bh[kt][nt][1], Bl[kt][nt][0], Bl[kt][nt][1]);
    }

    u32 ph[2][2], pl[2][2];
    #pragma unroll
    for (int kt2 = 0; kt2 < 2; kt2++) {
        int r0 = kt2 * 16 + 2 * c_;
        float p00 = 0.f, p01 = 0.f, p10 = 0.f, p11 = 0.f;
        if (g_ < 2) {
            p00 = mW[r0 * 2 + g_];       p01 = mW[(r0 + 1) * 2 + g_];
            p10 = mW[(r0 + 8) * 2 + g_]; p11 = mW[(r0 + 9) * 2 + g_];
        } else if (g_ < 4) {
            p00 = vW[r0 * 2 + g_ - 2];       p01 = vW[(r0 + 1) * 2 + g_ - 2];
            p10 = vW[(r0 + 8) * 2 + g_ - 2]; p11 = vW[(r0 + 9) * 2 + g_ - 2];
        }
        bsplit(p00, p01, ph[kt2][0], pl[kt2][0]);
        bsplit(p10, p11, ph[kt2][1], pl[kt2][1]);
    }
    float b20[4], b21[4];
    #pragma unroll
    for (int nt = 0; nt < 4; nt++) {
        b20[nt] = b2[nt * 8 + 2 * c_];
        b21[nt] = b2[nt * 8 + 2 * c_ + 1];
    }

    u32* myUh = &sUh[warp][0];
    u32* myUl = &sUl[warp][0];
    unsigned uhb = (unsigned)__cvta_generic_to_shared(myUh)
                 + (unsigned)((lane & 15) * 80 + (lane >> 4) * 16);
    unsigned ulb = (unsigned)__cvta_generic_to_shared(myUl)
                 + (unsigned)((lane & 15) * 80 + (lane >> 4) * 16);

    int tile0 = (blockIdx.x * 4 + warp) * TPW;
    #pragma unroll 1
    for (int it = 0; it < TPW; it++) {
        int tb = (tile0 + it) * 32;
        if (tb >= E) break;
        int idx = min(tb + lane, E - 1);   // clamped load (scatter stays guarded)
        int s_all = ei[idx];
        int t_all = ei[E + idx];

        gather32b(s_all, t_all, oct, sub, myUh, myUl);
        __syncwarp();

        #pragma unroll
        for (int mt = 0; mt < 2; mt++) {
            float d[4][4];
            #pragma unroll
            for (int nt = 0; nt < 4; nt++)
                #pragma unroll
                for (int j = 0; j < 4; j++) d[nt][j] = 0.f;
            #pragma unroll
            for (int kt = 0; kt < 2; kt++) {
                u32 ah[4], al[4];
                unsigned off = (unsigned)(mt * 16 * 80 + kt * 32);
                ldmx4(ah, uhb + off);
                ldmx4(al, ulb + off);
                #pragma unroll
                for (int nt = 0; nt < 4; nt++) {
                    mma16(d[nt], ah, Bh[kt][nt][0], Bh[kt][nt][1]);
                    mma16(d[nt], al, Bh[kt][nt][0], Bh[kt][nt][1]);
                    mma16(d[nt], ah, Bl[kt][nt][0], Bl[kt][nt][1]);
                }
            }

            float d2[4];
            proj_mma(d, b20, b21, ph, pl, d2);

            // cross-column exchange (xor 1 pairs c0<->c1, c2<->c3)
            float f2 = __shfl_xor_sync(0xffffffffu, d2[0], 1);
            float f3 = __shfl_xor_sync(0xffffffffu, d2[1], 1);
            float f6 = __shfl_xor_sync(0xffffffffu, d2[2], 1);
            float f7 = __shfl_xor_sync(0xffffffffu, d2[3], 1);

            int tga = __shfl_sync(0xffffffffu, t_all, mt * 16 + g_);
            int tgb = __shfl_sync(0xffffffffu, t_all, mt * 16 + 8 + g_);
            int ea = tb + mt * 16 + g_;
            int eb_ = ea + 8;
            if (c_ == 0 && ea < E) {
                // cols 0,1 local; cols 2,3 from c1
                red4(g_sumenc + (size_t)tga * 4, d2[0], d2[1], f2, f3);
                redf(&g_cnt[tga], 1.0f);
            }
            if (c_ == 1 && eb_ < E) {
                // cols 0,1 from c0 (f6,f7); cols 2,3 local (d2[2],d2[3])
                red4(g_sumenc + (size_t)tgb * 4, f6, f7, d2[2], d2[3]);
                redf(&g_cnt[tgb], 1.0f);
            }
        }
        __syncwarp();
    }
}

// ---- K4: per-node mid (also zeroes sumout) ----
__global__ void k_mid(const float* __restrict__ mb, const float* __restrict__ vb,
                      const float* __restrict__ dW1, const float* __restrict__ db1,
                      const float* __restrict__ eps2,
                      float* __restrict__ out_mu, float* __restrict__ out_lv, int n) {
    __shared__ float sWd[64], sWb[64], sdb1[32], smb[2], svb[2];
    int t = threadIdx.x;
    if (t < 32) {
        sdb1[t] = db1[t];
        sWd[t]      = dW1[t]      - dW1[64 + t];
        sWd[32 + t] = dW1[32 + t] - dW1[96 + t];
        sWb[t]      = dW1[64 + t];
        sWb[32 + t] = dW1[96 + t];
    }
    if (t < 2) { smb[t] = mb[t]; svb[t] = vb[t]; }
    __syncthreads();
    for (int i = blockIdx.x * blockDim.x + t; i < n; i += gridDim.x * blockDim.x) {
        float4 s = ((const float4*)g_sumenc)[i];
        float inv = 1.0f / fmaxf(g_cnt[i], 1.0f);
        float mu0 = s.x * inv + smb[0];
        float mu1 = s.y * inv + smb[1];
        float lv0 = s.z * inv + svb[0];
        float lv1 = s.w * inv + svb[1];
        float2 ep = ((const float2*)eps2)[i];
        float z0 = mu0 + ep.x * expf(0.5f * lv0);
        float z1 = mu1 + ep.y * expf(0.5f * lv1);
        ((float2*)out_mu)[i] = make_float2(mu0, mu1);
        ((float2*)out_lv)[i] = make_float2(lv0, lv1);
        float a[32], b[32];
        #pragma unroll
        for (int o = 0; o < 32; o++) {
            a[o] = sdb1[o] + z0 * sWd[o] + z1 * sWd[32 + o];
            b[o] = z0 * sWb[o] + z1 * sWb[32 + o];
        }
        float4* Ao = (float4*)(g_A + (size_t)i * 32);
        float4* Bo = (float4*)(g_B + (size_t)i * 32);
        #pragma unroll
        for (int q = 0; q < 8; q++) {
            Ao[q] = make_float4(a[4*q], a[4*q+1], a[4*q+2], a[4*q+3]);
            Bo[q] = make_float4(b[4*q], b[4*q+1], b[4*q+2], b[4*q+3]);
        }
        ((float4*)g_sumout)[i] = make_float4(0.f, 0.f, 0.f, 0.f);
    }
}

// ===================== decoder (b3 folded into k_out) =====================
__global__ void __launch_bounds__(128, 5) k_dec(const int* __restrict__ ei,
                                                const float* __restrict__ W2,
                                                const float* __restrict__ b2,
                                                const float* __restrict__ W3, int E) {
    __shared__ __align__(16) u32 sUh[4][32 * 20];
    __shared__ __align__(16) u32 sUl[4][32 * 20];
    __shared__ __align__(16) uint4 sB[256];

    fill_B16(W2, sB);
    __syncthreads();

    int lane = threadIdx.x & 31, warp = threadIdx.x >> 5;
    int g_ = lane >> 2, c_ = lane & 3;
    int oct = lane >> 3, sub = lane & 7;

    u32 Bh[2][4][2], Bl[2][4][2];
    {
        unsigned bb = (unsigned)__cvta_generic_to_shared(sB) + (unsigned)lane * 16u;
        #pragma unroll
        for (int kt = 0; kt < 2; kt++)
            #pragma unroll
            for (int nt = 0; nt < 4; nt++)
                lds128(bb + (unsigned)(kt * 4 + nt) * 512u,
                       Bh[kt][nt][0], Bh[kt][nt][1], Bl[kt][nt][0], Bl[kt][nt][1]);
    }

    u32 ph[2][2], pl[2][2];
    #pragma unroll
    for (int kt2 = 0; kt2 < 2; kt2++) {
        int r0 = kt2 * 16 + 2 * c_;
        float p00 = 0.f, p01 = 0.f, p10 = 0.f, p11 = 0.f;
        if (g_ < 4) {
            p00 = W3[r0 * 4 + g_];       p01 = W3[(r0 + 1) * 4 + g_];
            p10 = W3[(r0 + 8) * 4 + g_]; p11 = W3[(r0 + 9) * 4 + g_];
        }
        bsplit(p00, p01, ph[kt2][0], pl[kt2][0]);
        bsplit(p10, p11, ph[kt2][1], pl[kt2][1]);
    }
    float b20[4], b21[4];
    #pragma unroll
    for (int nt = 0; nt < 4; nt++) {
        b20[nt] = b2[nt * 8 + 2 * c_];
        b21[nt] = b2[nt * 8 + 2 * c_ + 1];
    }

    u32* myUh = &sUh[warp][0];
    u32* myUl = &sUl[warp][0];
    unsigned uhb = (unsigned)__cvta_generic_to_shared(myUh)
                 + (unsigned)((lane & 15) * 80 + (lane >> 4) * 16);
    unsigned ulb = (unsigned)__cvta_generic_to_shared(myUl)
                 + (unsigned)((lane & 15) * 80 + (lane >> 4) * 16);

    int tile0 = (blockIdx.x * 4 + warp) * TPW;
    #pragma unroll 1
    for (int it = 0; it < TPW; it++) {
        int tb = (tile0 + it) * 32;
        if (tb >= E) break;
        int idx = min(tb + lane, E - 1);
        int s_all = ei[idx];
        int t_all = ei[E + idx];

        gather32b(s_all, t_all, oct, sub, myUh, myUl);
        __syncwarp();

        #pragma unroll
        for (int mt = 0; mt < 2; mt++) {
            float d[4][4];
            #pragma unroll
            for (int nt = 0; nt < 4; nt++)
                #pragma unroll
                for (int j = 0; j < 4; j++) d[nt][j] = 0.f;
            #pragma unroll
            for (int kt = 0; kt < 2; kt++) {
                u32 ah[4], al[4];
                unsigned off = (unsigned)(mt * 16 * 80 + kt * 32);
                ldmx4(ah, uhb + off);
                ldmx4(al, ulb + off);
                #pragma unroll
                for (int nt = 0; nt < 4; nt++) {
                    mma16(d[nt], ah, Bh[kt][nt][0], Bh[kt][nt][1]);
                    mma16(d[nt], al, Bh[kt][nt][0], Bh[kt][nt][1]);
                    mma16(d[nt], ah, Bl[kt][nt][0], Bl[kt][nt][1]);
                }
            }

            float d2[4];
            proj_mma(d, b20, b21, ph, pl, d2);

            float f2 = __shfl_xor_sync(0xffffffffu, d2[0], 1);
            float f3 = __shfl_xor_sync(0xffffffffu, d2[1], 1);
            float f6 = __shfl_xor_sync(0xffffffffu, d2[2], 1);
            float f7 = __shfl_xor_sync(0xffffffffu, d2[3], 1);

            int tga = __shfl_sync(0xffffffffu, t_all, mt * 16 + g_);
            int tgb = __shfl_sync(0xffffffffu, t_all, mt * 16 + 8 + g_);
            int ea = tb + mt * 16 + g_;
            int eb_ = ea + 8;
            if (c_ == 0 && ea < E)
                red4(g_sumout + (size_t)tga * 4, d2[0], d2[1], f2, f3);
            if (c_ == 1 && eb_ < E)
                red4(g_sumout + (size_t)tgb * 4, f6, f7, d2[2], d2[3]);
        }
        __syncwarp();
    }
}

// ---- K6: per-node output mean (+ b3, gated on cnt>0 to match segment-mean semantics) ----
__global__ void k_out(const float* __restrict__ b3, float* __restrict__ out, int n) {
    float4 bb = *(const float4*)b3;
    for (int i = blockIdx.x * blockDim.x + threadIdx.x; i < n; i += gridDim.x * blockDim.x) {
        float cnt = g_cnt[i];
        float inv = 1.0f / fmaxf(cnt, 1.0f);
        float hb = (cnt > 0.f) ? 1.0f : 0.0f;
        float4 s = ((const float4*)g_sumout)[i];
        ((float4*)out)[i] = make_float4(s.x * inv + bb.x * hb, s.y * inv + bb.y * hb,
                                        s.z * inv + bb.z * hb, s.w * inv + bb.w * hb);
    }
}

extern "C" void kernel_launch(void* const* d_in, const int* in_sizes, int n_in,
                              void* d_out, int out_size) {
    const float* x     = (const float*)d_in[0];
    const int*   ei    = (const int*)d_in[1];
    const float* eps   = (const float*)d_in[2];
    const float* gamma = (const float*)d_in[3];
    const float* beta  = (const float*)d_in[4];
    const float* eW1   = (const float*)d_in[5];
    const float* eb1   = (const float*)d_in[6];
    const float* eW2   = (const float*)d_in[7];
    const float* eb2   = (const float*)d_in[8];
    const float* mW    = (const float*)d_in[9];
    const float* mb    = (const float*)d_in[10];
    const float* vW    = (const float*)d_in[11];
    const float* vb    = (const float*)d_in[12];
    const float* dW1   = (const float*)d_in[13];
    const float* db1   = (const float*)d_in[14];
    const float* dW2   = (const float*)d_in[15];
    const float* db2   = (const float*)d_in[16];
    const float* dW3   = (const float*)d_in[17];
    const float* db3   = (const float*)d_in[18];

    int n = in_sizes[0] / 4;
    int E = in_sizes[1] / 2;

    float* out    = (float*)d_out;
    float* out_mu = out + (size_t)n * 4;
    float* out_lv = out + (size_t)n * 6;

    int nb = (n + 255) / 256;
    int eb = (E + 128 * TPW - 1) / (128 * TPW);

    k_zero_s<<<1, 32>>>();
    k_stats<<<256, 256>>>((const float4*)x, n);
    k_pre<<<nb, 256>>>((const float4*)x, gamma, beta, eW1, eb1, n, 1.0f / (float)n);
    k_enc<<<eb, 128>>>(ei, eW2, eb2, mW, vW, E);
    k_mid<<<nb, 256>>>(mb, vb, dW1, db1, eps, out_mu, out_lv, n);
    k_dec<<<eb, 128>>>(ei, dW2, db2, dW3, E);
    k_out<<<nb, 256>>>(db3, out, n);
}